// round 15
// baseline (speedup 1.0000x reference)
#include <cuda_runtime.h>
#include <cuda_bf16.h>
#include <cstdint>
#include <math.h>

typedef unsigned int u32;

// Problem constants: B=1, S=2048, HIDDEN=2048, NUM_HEADS=16, MLA_DIM=HEAD_DIM=128
#define S_LEN 2048
#define HID   2048
#define NH    16
#define HD    128

// ---------------- scratch ----------------
__device__ float g_Q[S_LEN * HID];
__device__ float g_K[S_LEN * HID];
__device__ float g_Vt[HID * S_LEN];   // V transposed: [n = h*HD+d][s]
__device__ float g_AO[S_LEN * HID];
__device__ float g_Xt[S_LEN * HID];
__device__ float g_Wq[HID * HID];     // transposed [N][K], tf32-rounded
__device__ float g_Wk[HID * HID];
__device__ float g_Wv[HID * HID];
__device__ float g_Wo[HID * HID];

__device__ __forceinline__ float to_tf32(float x) {
    float r;
    asm("cvt.rna.tf32.f32 %0, %1;" : "=f"(r) : "f"(x));
    return r;
}

// fast exp2 for t <= 0: FMA/ALU pipes only. deg-6 Taylor, max rel err ~1.5e-5.
__device__ __forceinline__ float fexp2(float t) {
    t = fmaxf(t, -126.0f);
    float n = floorf(t);
    float f = t - n;
    float p = 1.5403530393381608e-4f;
    p = fmaf(p, f, 1.3333558146428443e-3f);
    p = fmaf(p, f, 9.6181291076284770e-3f);
    p = fmaf(p, f, 5.5504108664821580e-2f);
    p = fmaf(p, f, 2.4022650695910071e-1f);
    p = fmaf(p, f, 6.9314718055994531e-1f);
    p = fmaf(p, f, 1.0f);
    int e = (int)n;
    return p * __int_as_float((e + 127) << 23);
}

__device__ __forceinline__ void cp_async16(u32 dst, const void* src) {
    asm volatile("cp.async.cg.shared.global [%0], [%1], 16;" :: "r"(dst), "l"(src));
}
__device__ __forceinline__ void cp_commit() { asm volatile("cp.async.commit_group;"); }
__device__ __forceinline__ void cp_wait1()  { asm volatile("cp.async.wait_group 1;"); }
__device__ __forceinline__ void cp_wait0()  { asm volatile("cp.async.wait_group 0;"); }

__device__ __forceinline__ void mma_tf32(float* d, const u32* a, const u32* b) {
    asm volatile(
        "mma.sync.aligned.m16n8k8.row.col.f32.tf32.tf32.f32 "
        "{%0,%1,%2,%3}, {%4,%5,%6,%7}, {%8,%9}, {%0,%1,%2,%3};"
        : "+f"(d[0]), "+f"(d[1]), "+f"(d[2]), "+f"(d[3])
        : "r"(a[0]), "r"(a[1]), "r"(a[2]), "r"(a[3]), "r"(b[0]), "r"(b[1]));
}

__device__ __forceinline__ void ldsm4(u32& r0, u32& r1, u32& r2, u32& r3, u32 addr) {
    asm volatile("ldmatrix.sync.aligned.m8n8.x4.shared.b16 {%0,%1,%2,%3}, [%4];"
                 : "=r"(r0), "=r"(r1), "=r"(r2), "=r"(r3) : "r"(addr));
}

// ---------------- merged prepass: z=0 rounds X; z=1..4 transpose+round weights ----------------
__global__ void prepass_kernel(const float* __restrict__ x, float* __restrict__ xo,
                               const float* __restrict__ s0, float* __restrict__ d0,
                               const float* __restrict__ s1, float* __restrict__ d1,
                               const float* __restrict__ s2, float* __restrict__ d2,
                               const float* __restrict__ s3, float* __restrict__ d3) {
    if (blockIdx.z == 0) {
        int xcol = blockIdx.x * 32 + threadIdx.x;
        int yrow = blockIdx.y * 32 + threadIdx.y;
#pragma unroll
        for (int i = 0; i < 4; i++) {
            size_t idx = (size_t)(yrow + i * 8) * HID + xcol;
            xo[idx] = to_tf32(x[idx]);
        }
        return;
    }
    const float* in;
    float* out;
    switch (blockIdx.z) {
        case 1: in = s0; out = d0; break;
        case 2: in = s1; out = d1; break;
        case 3: in = s2; out = d2; break;
        default: in = s3; out = d3; break;
    }
    __shared__ float ts[32][33];
    int x0 = blockIdx.x * 32 + threadIdx.x;
    int y0 = blockIdx.y * 32 + threadIdx.y;
#pragma unroll
    for (int i = 0; i < 4; i++)
        ts[threadIdx.y + i * 8][threadIdx.x] = in[(size_t)(y0 + i * 8) * HID + x0];
    __syncthreads();
    int x2 = blockIdx.y * 32 + threadIdx.x;
    int y2 = blockIdx.x * 32 + threadIdx.y;
#pragma unroll
    for (int i = 0; i < 4; i++)
        out[(size_t)(y2 + i * 8) * HID + x2] = to_tf32(ts[threadIdx.x][threadIdx.y + i * 8]);
}

// ---------------- TF32 GEMM with ldmatrix + swizzled smem (proven) ----------------
#define TBM 128
#define TBN 128
#define TBK 32
#define TSZ 4096
#define GEMM_SMEM_BYTES (3 * 2 * TSZ * 4)
#define NKIT (HID / TBK)

template <bool TRANS_Z2>
__global__ __launch_bounds__(256, 2) void tf32_gemm_ldsm(
    const float* __restrict__ A,
    const float* __restrict__ B0, const float* __restrict__ B1, const float* __restrict__ B2,
    float* __restrict__ C0, float* __restrict__ C1, float* __restrict__ C2) {
    const float* B = (blockIdx.z == 0) ? B0 : ((blockIdx.z == 1) ? B1 : B2);
    float* C       = (blockIdx.z == 0) ? C0 : ((blockIdx.z == 1) ? C1 : C2);
    const bool trans_out = TRANS_Z2 && (blockIdx.z == 2);

    const int K = HID, N = HID;
    extern __shared__ float gsm[];
    float* As = gsm;
    float* Bs = gsm + 3 * TSZ;

    const int tid  = threadIdx.x;
    const int lane = tid & 31;
    const int warp = tid >> 5;
    const int warpM = warp >> 1;
    const int warpN = warp & 1;
    const int g  = lane >> 2;
    const int tg = lane & 3;

    const int row0 = blockIdx.y * TBM;
    const int col0 = blockIdx.x * TBN;

    const int r_ld = tid >> 3, c_ld = tid & 7;
    const float* gA = A + (size_t)(row0 + r_ld) * K + c_ld * 4;
    const float* gB = B + (size_t)(col0 + r_ld) * K + c_ld * 4;
    const u32 smA = (u32)__cvta_generic_to_shared(As);
    const u32 smB = (u32)__cvta_generic_to_shared(Bs);
    const u32 dOff = (u32)((r_ld * 8 + (c_ld ^ (r_ld & 7))) << 4);

    const int l8 = lane & 7;
    const int a_m  = warpM * 32 + l8 + (((lane >> 3) & 1) << 3);
    const int a_cs = (lane >> 4) & 1;
    const int b_n  = warpN * 64 + l8 + (((lane >> 4) & 1) << 3);
    const int b_cs = (lane >> 3) & 1;

    float acc[2][8][4];
#pragma unroll
    for (int mt = 0; mt < 2; mt++)
#pragma unroll
        for (int nt = 0; nt < 8; nt++)
#pragma unroll
            for (int r = 0; r < 4; r++) acc[mt][nt][r] = 0.f;

#pragma unroll
    for (int p = 0; p < 2; p++) {
        int kk = p * TBK;
        u32 ad = smA + (u32)(p * TSZ * 4) + dOff;
        u32 bd = smB + (u32)(p * TSZ * 4) + dOff;
#pragma unroll
        for (int q = 0; q < 4; q++) {
            cp_async16(ad + (u32)(q * 4096), gA + kk + (size_t)(q * 32) * K);
            cp_async16(bd + (u32)(q * 4096), gB + kk + (size_t)(q * 32) * K);
        }
        cp_commit();
    }

    int st = 0, ld = 2;
    for (int kb = 0; kb < NKIT; kb++) {
        if (kb == NKIT - 1) cp_wait0(); else cp_wait1();
        __syncthreads();

        if (kb + 2 < NKIT) {
            int kk = (kb + 2) * TBK;
            u32 ad = smA + (u32)(ld * TSZ * 4) + dOff;
            u32 bd = smB + (u32)(ld * TSZ * 4) + dOff;
#pragma unroll
            for (int q = 0; q < 4; q++) {
                cp_async16(ad + (u32)(q * 4096), gA + kk + (size_t)(q * 32) * K);
                cp_async16(bd + (u32)(q * 4096), gB + kk + (size_t)(q * 32) * K);
            }
            cp_commit();
        }

        const u32 aStage = smA + (u32)(st * TSZ * 4);
        const u32 bStage = smB + (u32)(st * TSZ * 4);

        u32 af[2][2][4];
        u32 bf[2][8][2];

#pragma unroll
        for (int mt = 0; mt < 2; mt++)
            ldsm4(af[0][mt][0], af[0][mt][1], af[0][mt][2], af[0][mt][3],
                  aStage + (u32)((a_m + mt * 16) * 128 + ((a_cs ^ l8) << 4)));
#pragma unroll
        for (int p = 0; p < 4; p++)
            ldsm4(bf[0][2 * p][0], bf[0][2 * p][1], bf[0][2 * p + 1][0], bf[0][2 * p + 1][1],
                  bStage + (u32)((b_n + p * 16) * 128 + ((b_cs ^ l8) << 4)));

#pragma unroll
        for (int kg = 0; kg < 4; kg++) {
            const int cur = kg & 1, nxt = cur ^ 1;
            if (kg < 3) {
                const int c = 2 * (kg + 1);
#pragma unroll
                for (int mt = 0; mt < 2; mt++)
                    ldsm4(af[nxt][mt][0], af[nxt][mt][1], af[nxt][mt][2], af[nxt][mt][3],
                          aStage + (u32)((a_m + mt * 16) * 128 + (((c + a_cs) ^ l8) << 4)));
#pragma unroll
                for (int p = 0; p < 4; p++)
                    ldsm4(bf[nxt][2 * p][0], bf[nxt][2 * p][1], bf[nxt][2 * p + 1][0], bf[nxt][2 * p + 1][1],
                          bStage + (u32)((b_n + p * 16) * 128 + (((c + b_cs) ^ l8) << 4)));
            }
#pragma unroll
            for (int mt = 0; mt < 2; mt++)
#pragma unroll
                for (int nt = 0; nt < 8; nt++)
                    mma_tf32(acc[mt][nt], af[cur][mt], bf[cur][nt]);
        }

        st = (st == 2) ? 0 : st + 1;
        ld = (ld == 2) ? 0 : ld + 1;
    }

    if (trans_out) {
#pragma unroll
        for (int mt = 0; mt < 2; mt++) {
            int r = row0 + warpM * 32 + mt * 16 + g;
#pragma unroll
            for (int nt = 0; nt < 8; nt++) {
                int c = col0 + warpN * 64 + nt * 8 + 2 * tg;
                C[(size_t)c * N + r]           = to_tf32(acc[mt][nt][0]);
                C[(size_t)(c + 1) * N + r]     = to_tf32(acc[mt][nt][1]);
                C[(size_t)c * N + r + 8]       = to_tf32(acc[mt][nt][2]);
                C[(size_t)(c + 1) * N + r + 8] = to_tf32(acc[mt][nt][3]);
            }
        }
    } else {
#pragma unroll
        for (int mt = 0; mt < 2; mt++) {
            int r = row0 + warpM * 32 + mt * 16 + g;
#pragma unroll
            for (int nt = 0; nt < 8; nt++) {
                int c = col0 + warpN * 64 + nt * 8 + 2 * tg;
                *(float2*)&C[(size_t)r * N + c]       = make_float2(acc[mt][nt][0], acc[mt][nt][1]);
                *(float2*)&C[(size_t)(r + 8) * N + c] = make_float2(acc[mt][nt][2], acc[mt][nt][3]);
            }
        }
    }
}

// ---------------- RoPE (in-place; K output tf32-rounded) ----------------
__global__ void rope_kernel(float* __restrict__ Q, float* __restrict__ K) {
    int idx = blockIdx.x * blockDim.x + threadIdx.x;
    int j = idx & 63;
    int h = (idx >> 6) & (NH - 1);
    int t = idx >> 10;

    float expo   = (float)(2 * j) * (1.0f / 128.0f);
    float invfrq = expf(-expo * 9.210340371976184f);
    float ang    = (float)t * invfrq;
    float sv, cv;
    sincosf(ang, &sv, &cv);

    int base = t * HID + h * HD + j;
    float q1 = Q[base], q2 = Q[base + 64];
    Q[base]      = q1 * cv - q2 * sv;
    Q[base + 64] = q2 * cv + q1 * sv;
    float k1 = K[base], k2 = K[base + 64];
    K[base]      = to_tf32(k1 * cv - k2 * sv);
    K[base + 64] = to_tf32(k2 * cv + k1 * sv);
}

// ---------------- Flash attention v3: BM=128, 8Mx1N warps, warp-local softmax ----------------
// Q tile: 128 rows x 128 floats (512 B/row swizzled). K: 64x128 (2 stages).
// Vt: 128 d-rows x 64 (256 B/row swizzled, 2 stages). P: 128 x SLD (per-warp 16 rows).
#define QKROWB 512
#define Q_TILE_FLOATS (128 * 128)    // 16384
#define K_TILE_FLOATS (64 * 128)     // 8192
#define VT_TILE_FLOATS (128 * 64)    // 8192
#define SLD 68

#define FM_SMEM_FLOATS (Q_TILE_FLOATS + 2*K_TILE_FLOATS + 2*VT_TILE_FLOATS + 128*SLD)
#define FM_SMEM_BYTES  (FM_SMEM_FLOATS * 4)   // 231424

__global__ __launch_bounds__(256, 1) void flash_mma_kernel(const float* __restrict__ Q,
                                                           const float* __restrict__ K,
                                                           const float* __restrict__ Vt) {
    extern __shared__ float sm[];
    float* Qs  = sm;                           // 128 x 128 swizzled
    float* Ks  = Qs + Q_TILE_FLOATS;           // 2 stages, 64 x 128 swizzled
    float* Vts = Ks + 2 * K_TILE_FLOATS;       // 2 stages, 128 x 64 swizzled
    float* Ss  = Vts + 2 * VT_TILE_FLOATS;     // 128 x SLD (P; per-warp rows)

    const int qb = gridDim.x - 1 - blockIdx.x;   // heaviest first
    const int h  = blockIdx.y;
    const int tid  = threadIdx.x;
    const int lane = tid & 31, warp = tid >> 5;
    const int g = lane >> 2, tg = lane & 3;
    const int m0 = warp * 16;                  // 8 warps x 16 rows = 128
    const int qrow0 = qb * 128;
    const float scale = 0.08838834764831845f * 1.4426950408889634f;
    const int r0 = m0 + g, r1 = m0 + g + 8;
    const int nkb = 2 * qb + 2;

    const int l8 = lane & 7;
    const int a_m  = m0 + l8 + (((lane >> 3) & 1) << 3);
    const int a_cs = (lane >> 4) & 1;
    const int b_n  = l8 + (((lane >> 4) & 1) << 3);     // K/Vt frag row base (tile-local)
    const int b_cs = (lane >> 3) & 1;

    const u32 qsmB = (u32)__cvta_generic_to_shared(Qs);
    const u32 ksmB = (u32)__cvta_generic_to_shared(Ks);
    const u32 vsmB = (u32)__cvta_generic_to_shared(Vts);
    const u32 ssmB = (u32)__cvta_generic_to_shared(Ss);

    // Q tile: 128x128, scale + tf32-round, swizzled
    for (int i = tid; i < 128 * 32; i += 256) {
        int r = i >> 5, cc = i & 31;
        float4 v = *(const float4*)&Q[(size_t)(qrow0 + r) * HID + h * HD + cc * 4];
        v.x = to_tf32(v.x * scale); v.y = to_tf32(v.y * scale);
        v.z = to_tf32(v.z * scale); v.w = to_tf32(v.w * scale);
        *(float4*)((char*)Qs + r * QKROWB + ((cc ^ (r & 7)) << 4)) = v;
    }

    // prefetch kb=0 into stage 0
#pragma unroll
    for (int t = 0; t < 8; t++) {
        int i = tid + t * 256;
        {
            int r = i >> 5, cc = i & 31;
            cp_async16(ksmB + (u32)(r * QKROWB + ((cc ^ (r & 7)) << 4)),
                       &K[(size_t)r * HID + h * HD + cc * 4]);
        }
        {
            int r = i >> 4, cc = i & 15;
            cp_async16(vsmB + (u32)(r * 256 + ((cc ^ (r & 7)) << 4)),
                       &Vt[(size_t)(h * HD + r) * S_LEN + cc * 4]);
        }
    }
    cp_commit();

    float oac[2][8][4];
#pragma unroll
    for (int dh = 0; dh < 2; dh++)
#pragma unroll
        for (int nt = 0; nt < 8; nt++)
#pragma unroll
            for (int r = 0; r < 4; r++) oac[dh][nt][r] = 0.f;
    float m_i0 = -1e30f, m_i1 = -1e30f, l_i0 = 0.f, l_i1 = 0.f;

    for (int kb = 0; kb < nkb; kb++) {
        int st = kb & 1;
        cp_wait0();
        __syncthreads();

        if (kb + 1 < nkb) {
            int krow0 = (kb + 1) * 64;
            u32 ko = ksmB + (u32)((st ^ 1) * K_TILE_FLOATS * 4);
            u32 vo = vsmB + (u32)((st ^ 1) * VT_TILE_FLOATS * 4);
#pragma unroll
            for (int t = 0; t < 8; t++) {
                int i = tid + t * 256;
                {
                    int r = i >> 5, cc = i & 31;
                    cp_async16(ko + (u32)(r * QKROWB + ((cc ^ (r & 7)) << 4)),
                               &K[(size_t)(krow0 + r) * HID + h * HD + cc * 4]);
                }
                {
                    int r = i >> 4, cc = i & 15;
                    cp_async16(vo + (u32)(r * 256 + ((cc ^ (r & 7)) << 4)),
                               &Vt[(size_t)(h * HD + r) * S_LEN + krow0 + cc * 4]);
                }
            }
            cp_commit();
        }

        const u32 kStage = ksmB + (u32)(st * K_TILE_FLOATS * 4);
        const u32 vStage = vsmB + (u32)(st * VT_TILE_FLOATS * 4);

        // ---- S = Q @ K^T : warp computes 16 rows x 64 cols ----
        float sac[8][4];
#pragma unroll
        for (int nt = 0; nt < 8; nt++)
#pragma unroll
            for (int r = 0; r < 4; r++) sac[nt][r] = 0.f;

        {
            u32 qa[2][4], kf[2][8][2];
            ldsm4(qa[0][0], qa[0][1], qa[0][2], qa[0][3],
                  qsmB + (u32)(a_m * QKROWB + ((a_cs ^ l8) << 4)));
#pragma unroll
            for (int p = 0; p < 4; p++)
                ldsm4(kf[0][2 * p][0], kf[0][2 * p][1], kf[0][2 * p + 1][0], kf[0][2 * p + 1][1],
                      kStage + (u32)((b_n + p * 16) * QKROWB + ((b_cs ^ l8) << 4)));
#pragma unroll
            for (int kk = 0; kk < 16; kk++) {
                const int cur = kk & 1, nxt = cur ^ 1;
                if (kk < 15) {
                    const int c = 2 * (kk + 1);
                    ldsm4(qa[nxt][0], qa[nxt][1], qa[nxt][2], qa[nxt][3],
                          qsmB + (u32)(a_m * QKROWB + (((c + a_cs) ^ l8) << 4)));
#pragma unroll
                    for (int p = 0; p < 4; p++)
                        ldsm4(kf[nxt][2 * p][0], kf[nxt][2 * p][1], kf[nxt][2 * p + 1][0], kf[nxt][2 * p + 1][1],
                              kStage + (u32)((b_n + p * 16) * QKROWB + (((c + b_cs) ^ l8) << 4)));
                }
#pragma unroll
                for (int nt = 0; nt < 8; nt++)
                    mma_tf32(sac[nt], qa[cur], kf[cur][nt]);
            }
        }

        // ---- causal mask (only last two kv blocks can clip) ----
        if (kb >= 2 * qb) {
            int cbase = kb * 64 - qrow0;   // col_local_global - row base
#pragma unroll
            for (int nt = 0; nt < 8; nt++) {
                int col = cbase + nt * 8 + 2 * tg;
                if (col     > r0) sac[nt][0] = -1e30f;
                if (col + 1 > r0) sac[nt][1] = -1e30f;
                if (col     > r1) sac[nt][2] = -1e30f;
                if (col + 1 > r1) sac[nt][3] = -1e30f;
            }
        }

        // ---- warp-local softmax ----
        float mx0 = -1e30f, mx1 = -1e30f;
#pragma unroll
        for (int nt = 0; nt < 8; nt++) {
            mx0 = fmaxf(mx0, fmaxf(sac[nt][0], sac[nt][1]));
            mx1 = fmaxf(mx1, fmaxf(sac[nt][2], sac[nt][3]));
        }
        mx0 = fmaxf(mx0, __shfl_xor_sync(0xffffffffu, mx0, 1));
        mx0 = fmaxf(mx0, __shfl_xor_sync(0xffffffffu, mx0, 2));
        mx1 = fmaxf(mx1, __shfl_xor_sync(0xffffffffu, mx1, 1));
        mx1 = fmaxf(mx1, __shfl_xor_sync(0xffffffffu, mx1, 2));
        float mnew0 = fmaxf(m_i0, mx0), mnew1 = fmaxf(m_i1, mx1);
        float alpha0 = fexp2(m_i0 - mnew0), alpha1 = fexp2(m_i1 - mnew1);

        float s0 = 0.f, s1 = 0.f;
#pragma unroll
        for (int nt = 0; nt < 8; nt++) {
            int col = nt * 8 + 2 * tg;
            float p00 = fexp2(sac[nt][0] - mnew0);
            float p01 = fexp2(sac[nt][1] - mnew0);
            float p10 = fexp2(sac[nt][2] - mnew1);
            float p11 = fexp2(sac[nt][3] - mnew1);
            s0 += p00 + p01;
            s1 += p10 + p11;
            Ss[r0 * SLD + col]     = to_tf32(p00);
            Ss[r0 * SLD + col + 1] = to_tf32(p01);
            Ss[r1 * SLD + col]     = to_tf32(p10);
            Ss[r1 * SLD + col + 1] = to_tf32(p11);
        }
        s0 += __shfl_xor_sync(0xffffffffu, s0, 1);
        s0 += __shfl_xor_sync(0xffffffffu, s0, 2);
        s1 += __shfl_xor_sync(0xffffffffu, s1, 1);
        s1 += __shfl_xor_sync(0xffffffffu, s1, 2);
        l_i0 = l_i0 * alpha0 + s0;
        l_i1 = l_i1 * alpha1 + s1;
        m_i0 = mnew0; m_i1 = mnew1;
        __syncwarp();   // P visible within the warp before ldmatrix

        // ---- O = O*alpha + P @ Vt^T, two d-halves ----
#pragma unroll
        for (int dh = 0; dh < 2; dh++)
#pragma unroll
            for (int nt = 0; nt < 8; nt++) {
                oac[dh][nt][0] *= alpha0; oac[dh][nt][1] *= alpha0;
                oac[dh][nt][2] *= alpha1; oac[dh][nt][3] *= alpha1;
            }
#pragma unroll
        for (int dh = 0; dh < 2; dh++) {
            u32 pa[2][4], vf[2][8][2];
            ldsm4(pa[0][0], pa[0][1], pa[0][2], pa[0][3],
                  ssmB + (u32)((a_m * SLD + a_cs * 4) << 2));
#pragma unroll
            for (int p = 0; p < 4; p++)
                ldsm4(vf[0][2 * p][0], vf[0][2 * p][1], vf[0][2 * p + 1][0], vf[0][2 * p + 1][1],
                      vStage + (u32)((b_n + (dh * 4 + p) * 16) * 256 + ((b_cs ^ l8) << 4)));
#pragma unroll
            for (int kk = 0; kk < 8; kk++) {
                const int cur = kk & 1, nxt = cur ^ 1;
                if (kk < 7) {
                    const int k0 = (kk + 1) * 8;
                    const int c = 2 * (kk + 1);
                    ldsm4(pa[nxt][0], pa[nxt][1], pa[nxt][2], pa[nxt][3],
                          ssmB + (u32)((a_m * SLD + k0 + a_cs * 4) << 2));
#pragma unroll
                    for (int p = 0; p < 4; p++)
                        ldsm4(vf[nxt][2 * p][0], vf[nxt][2 * p][1], vf[nxt][2 * p + 1][0], vf[nxt][2 * p + 1][1],
                              vStage + (u32)((b_n + (dh * 4 + p) * 16) * 256 + (((c + b_cs) ^ l8) << 4)));
                }
#pragma unroll
                for (int nt = 0; nt < 8; nt++)
                    mma_tf32(oac[dh][nt], pa[cur], vf[cur][nt]);
            }
        }
    }

    float inv0 = 1.0f / l_i0;
    float inv1 = 1.0f / l_i1;
    int gr0 = qrow0 + r0, gr1 = qrow0 + r1;
#pragma unroll
    for (int dh = 0; dh < 2; dh++)
#pragma unroll
        for (int nt = 0; nt < 8; nt++) {
            int col = dh * 64 + nt * 8 + 2 * tg;
            float2 w0 = make_float2(to_tf32(oac[dh][nt][0] * inv0), to_tf32(oac[dh][nt][1] * inv0));
            float2 w1 = make_float2(to_tf32(oac[dh][nt][2] * inv1), to_tf32(oac[dh][nt][3] * inv1));
            *(float2*)&g_AO[(size_t)gr0 * HID + h * HD + col] = w0;
            *(float2*)&g_AO[(size_t)gr1 * HID + h * HD + col] = w1;
        }
}

// ---------------- launch ----------------
extern "C" void kernel_launch(void* const* d_in, const int* in_sizes, int n_in,
                              void* d_out, int out_size) {
    const float* X  = (const float*)d_in[0];
    const float* wq = (const float*)d_in[1];
    const float* wk = (const float*)d_in[2];
    const float* wv = (const float*)d_in[3];
    const float* wo = (const float*)d_in[4];
    float* out = (float*)d_out;

    float *Q, *K, *Vt, *AO, *Xt, *Wq, *Wk, *Wv, *Wo;
    cudaGetSymbolAddress((void**)&Q,  g_Q);
    cudaGetSymbolAddress((void**)&K,  g_K);
    cudaGetSymbolAddress((void**)&Vt, g_Vt);
    cudaGetSymbolAddress((void**)&AO, g_AO);
    cudaGetSymbolAddress((void**)&Xt, g_Xt);
    cudaGetSymbolAddress((void**)&Wq, g_Wq);
    cudaGetSymbolAddress((void**)&Wk, g_Wk);
    cudaGetSymbolAddress((void**)&Wv, g_Wv);
    cudaGetSymbolAddress((void**)&Wo, g_Wo);

    cudaFuncSetAttribute(tf32_gemm_ldsm<true>, cudaFuncAttributeMaxDynamicSharedMemorySize,
                         GEMM_SMEM_BYTES);
    cudaFuncSetAttribute(tf32_gemm_ldsm<false>, cudaFuncAttributeMaxDynamicSharedMemorySize,
                         GEMM_SMEM_BYTES);
    cudaFuncSetAttribute(flash_mma_kernel, cudaFuncAttributeMaxDynamicSharedMemorySize,
                         FM_SMEM_BYTES);

    prepass_kernel<<<dim3(64, 64, 5), dim3(32, 8)>>>(
        X, Xt, wq, Wq, wk, Wk, wv, Wv, wo, Wo);

    tf32_gemm_ldsm<true><<<dim3(16, 16, 3), 256, GEMM_SMEM_BYTES>>>(
        Xt, Wq, Wk, Wv, Q, K, Vt);

    rope_kernel<<<(S_LEN * NH * 64) / 256, 256>>>(Q, K);

    flash_mma_kernel<<<dim3(S_LEN / 128, NH), 256, FM_SMEM_BYTES>>>(Q, K, Vt);

    tf32_gemm_ldsm<false><<<dim3(16, 16, 1), 256, GEMM_SMEM_BYTES>>>(
        AO, Wo, Wo, Wo, out, out, out);

    (void)in_sizes; (void)n_in; (void)out_size;
}

// round 16
// speedup vs baseline: 1.0195x; 1.0195x over previous
#include <cuda_runtime.h>
#include <cuda_bf16.h>
#include <cstdint>
#include <math.h>

typedef unsigned int u32;

// Problem constants: B=1, S=2048, HIDDEN=2048, NUM_HEADS=16, MLA_DIM=HEAD_DIM=128
#define S_LEN 2048
#define HID   2048
#define NH    16
#define HD    128

// ---------------- scratch ----------------
__device__ float g_Q[S_LEN * HID];
__device__ float g_K[S_LEN * HID];
__device__ float g_Vt[HID * S_LEN];   // V transposed: [n = h*HD+d][s]
__device__ float g_AO[S_LEN * HID];
__device__ float g_Xt[S_LEN * HID];
__device__ float g_Wq[HID * HID];     // transposed [N][K], tf32-rounded
__device__ float g_Wk[HID * HID];
__device__ float g_Wv[HID * HID];
__device__ float g_Wo[HID * HID];

__device__ __forceinline__ float to_tf32(float x) {
    float r;
    asm("cvt.rna.tf32.f32 %0, %1;" : "=f"(r) : "f"(x));
    return r;
}

// fast exp2 for t <= 0: FMA/ALU pipes only. deg-6 Taylor, max rel err ~1.5e-5.
__device__ __forceinline__ float fexp2(float t) {
    t = fmaxf(t, -126.0f);
    float n = floorf(t);
    float f = t - n;
    float p = 1.5403530393381608e-4f;
    p = fmaf(p, f, 1.3333558146428443e-3f);
    p = fmaf(p, f, 9.6181291076284770e-3f);
    p = fmaf(p, f, 5.5504108664821580e-2f);
    p = fmaf(p, f, 2.4022650695910071e-1f);
    p = fmaf(p, f, 6.9314718055994531e-1f);
    p = fmaf(p, f, 1.0f);
    int e = (int)n;
    return p * __int_as_float((e + 127) << 23);
}

__device__ __forceinline__ void cp_async16(u32 dst, const void* src) {
    asm volatile("cp.async.cg.shared.global [%0], [%1], 16;" :: "r"(dst), "l"(src));
}
__device__ __forceinline__ void cp_commit() { asm volatile("cp.async.commit_group;"); }
__device__ __forceinline__ void cp_wait1()  { asm volatile("cp.async.wait_group 1;"); }
__device__ __forceinline__ void cp_wait0()  { asm volatile("cp.async.wait_group 0;"); }

__device__ __forceinline__ void bar_pair(int id) {
    asm volatile("bar.sync %0, 64;" :: "r"(id) : "memory");
}

__device__ __forceinline__ void mma_tf32(float* d, const u32* a, const u32* b) {
    asm volatile(
        "mma.sync.aligned.m16n8k8.row.col.f32.tf32.tf32.f32 "
        "{%0,%1,%2,%3}, {%4,%5,%6,%7}, {%8,%9}, {%0,%1,%2,%3};"
        : "+f"(d[0]), "+f"(d[1]), "+f"(d[2]), "+f"(d[3])
        : "r"(a[0]), "r"(a[1]), "r"(a[2]), "r"(a[3]), "r"(b[0]), "r"(b[1]));
}

__device__ __forceinline__ void ldsm4(u32& r0, u32& r1, u32& r2, u32& r3, u32 addr) {
    asm volatile("ldmatrix.sync.aligned.m8n8.x4.shared.b16 {%0,%1,%2,%3}, [%4];"
                 : "=r"(r0), "=r"(r1), "=r"(r2), "=r"(r3) : "r"(addr));
}

// ---------------- merged prepass: z=0 rounds X; z=1..4 transpose+round weights ----------------
__global__ void prepass_kernel(const float* __restrict__ x, float* __restrict__ xo,
                               const float* __restrict__ s0, float* __restrict__ d0,
                               const float* __restrict__ s1, float* __restrict__ d1,
                               const float* __restrict__ s2, float* __restrict__ d2,
                               const float* __restrict__ s3, float* __restrict__ d3) {
    if (blockIdx.z == 0) {
        int xcol = blockIdx.x * 32 + threadIdx.x;
        int yrow = blockIdx.y * 32 + threadIdx.y;
#pragma unroll
        for (int i = 0; i < 4; i++) {
            size_t idx = (size_t)(yrow + i * 8) * HID + xcol;
            xo[idx] = to_tf32(x[idx]);
        }
        return;
    }
    const float* in;
    float* out;
    switch (blockIdx.z) {
        case 1: in = s0; out = d0; break;
        case 2: in = s1; out = d1; break;
        case 3: in = s2; out = d2; break;
        default: in = s3; out = d3; break;
    }
    __shared__ float ts[32][33];
    int x0 = blockIdx.x * 32 + threadIdx.x;
    int y0 = blockIdx.y * 32 + threadIdx.y;
#pragma unroll
    for (int i = 0; i < 4; i++)
        ts[threadIdx.y + i * 8][threadIdx.x] = in[(size_t)(y0 + i * 8) * HID + x0];
    __syncthreads();
    int x2 = blockIdx.y * 32 + threadIdx.x;
    int y2 = blockIdx.x * 32 + threadIdx.y;
#pragma unroll
    for (int i = 0; i < 4; i++)
        out[(size_t)(y2 + i * 8) * HID + x2] = to_tf32(ts[threadIdx.x][threadIdx.y + i * 8]);
}

// ---------------- TF32 GEMM with ldmatrix + swizzled smem (proven) ----------------
#define TBM 128
#define TBN 128
#define TBK 32
#define TSZ 4096
#define GEMM_SMEM_BYTES (3 * 2 * TSZ * 4)
#define NKIT (HID / TBK)

template <bool TRANS_Z2>
__global__ __launch_bounds__(256, 2) void tf32_gemm_ldsm(
    const float* __restrict__ A,
    const float* __restrict__ B0, const float* __restrict__ B1, const float* __restrict__ B2,
    float* __restrict__ C0, float* __restrict__ C1, float* __restrict__ C2) {
    const float* B = (blockIdx.z == 0) ? B0 : ((blockIdx.z == 1) ? B1 : B2);
    float* C       = (blockIdx.z == 0) ? C0 : ((blockIdx.z == 1) ? C1 : C2);
    const bool trans_out = TRANS_Z2 && (blockIdx.z == 2);

    const int K = HID, N = HID;
    extern __shared__ float gsm[];
    float* As = gsm;
    float* Bs = gsm + 3 * TSZ;

    const int tid  = threadIdx.x;
    const int lane = tid & 31;
    const int warp = tid >> 5;
    const int warpM = warp >> 1;
    const int warpN = warp & 1;
    const int g  = lane >> 2;
    const int tg = lane & 3;

    const int row0 = blockIdx.y * TBM;
    const int col0 = blockIdx.x * TBN;

    const int r_ld = tid >> 3, c_ld = tid & 7;
    const float* gA = A + (size_t)(row0 + r_ld) * K + c_ld * 4;
    const float* gB = B + (size_t)(col0 + r_ld) * K + c_ld * 4;
    const u32 smA = (u32)__cvta_generic_to_shared(As);
    const u32 smB = (u32)__cvta_generic_to_shared(Bs);
    const u32 dOff = (u32)((r_ld * 8 + (c_ld ^ (r_ld & 7))) << 4);

    const int l8 = lane & 7;
    const int a_m  = warpM * 32 + l8 + (((lane >> 3) & 1) << 3);
    const int a_cs = (lane >> 4) & 1;
    const int b_n  = warpN * 64 + l8 + (((lane >> 4) & 1) << 3);
    const int b_cs = (lane >> 3) & 1;

    float acc[2][8][4];
#pragma unroll
    for (int mt = 0; mt < 2; mt++)
#pragma unroll
        for (int nt = 0; nt < 8; nt++)
#pragma unroll
            for (int r = 0; r < 4; r++) acc[mt][nt][r] = 0.f;

#pragma unroll
    for (int p = 0; p < 2; p++) {
        int kk = p * TBK;
        u32 ad = smA + (u32)(p * TSZ * 4) + dOff;
        u32 bd = smB + (u32)(p * TSZ * 4) + dOff;
#pragma unroll
        for (int q = 0; q < 4; q++) {
            cp_async16(ad + (u32)(q * 4096), gA + kk + (size_t)(q * 32) * K);
            cp_async16(bd + (u32)(q * 4096), gB + kk + (size_t)(q * 32) * K);
        }
        cp_commit();
    }

    int st = 0, ld = 2;
    for (int kb = 0; kb < NKIT; kb++) {
        if (kb == NKIT - 1) cp_wait0(); else cp_wait1();
        __syncthreads();

        if (kb + 2 < NKIT) {
            int kk = (kb + 2) * TBK;
            u32 ad = smA + (u32)(ld * TSZ * 4) + dOff;
            u32 bd = smB + (u32)(ld * TSZ * 4) + dOff;
#pragma unroll
            for (int q = 0; q < 4; q++) {
                cp_async16(ad + (u32)(q * 4096), gA + kk + (size_t)(q * 32) * K);
                cp_async16(bd + (u32)(q * 4096), gB + kk + (size_t)(q * 32) * K);
            }
            cp_commit();
        }

        const u32 aStage = smA + (u32)(st * TSZ * 4);
        const u32 bStage = smB + (u32)(st * TSZ * 4);

        u32 af[2][2][4];
        u32 bf[2][8][2];

#pragma unroll
        for (int mt = 0; mt < 2; mt++)
            ldsm4(af[0][mt][0], af[0][mt][1], af[0][mt][2], af[0][mt][3],
                  aStage + (u32)((a_m + mt * 16) * 128 + ((a_cs ^ l8) << 4)));
#pragma unroll
        for (int p = 0; p < 4; p++)
            ldsm4(bf[0][2 * p][0], bf[0][2 * p][1], bf[0][2 * p + 1][0], bf[0][2 * p + 1][1],
                  bStage + (u32)((b_n + p * 16) * 128 + ((b_cs ^ l8) << 4)));

#pragma unroll
        for (int kg = 0; kg < 4; kg++) {
            const int cur = kg & 1, nxt = cur ^ 1;
            if (kg < 3) {
                const int c = 2 * (kg + 1);
#pragma unroll
                for (int mt = 0; mt < 2; mt++)
                    ldsm4(af[nxt][mt][0], af[nxt][mt][1], af[nxt][mt][2], af[nxt][mt][3],
                          aStage + (u32)((a_m + mt * 16) * 128 + (((c + a_cs) ^ l8) << 4)));
#pragma unroll
                for (int p = 0; p < 4; p++)
                    ldsm4(bf[nxt][2 * p][0], bf[nxt][2 * p][1], bf[nxt][2 * p + 1][0], bf[nxt][2 * p + 1][1],
                          bStage + (u32)((b_n + p * 16) * 128 + (((c + b_cs) ^ l8) << 4)));
            }
#pragma unroll
            for (int mt = 0; mt < 2; mt++)
#pragma unroll
                for (int nt = 0; nt < 8; nt++)
                    mma_tf32(acc[mt][nt], af[cur][mt], bf[cur][nt]);
        }

        st = (st == 2) ? 0 : st + 1;
        ld = (ld == 2) ? 0 : ld + 1;
    }

    if (trans_out) {
#pragma unroll
        for (int mt = 0; mt < 2; mt++) {
            int r = row0 + warpM * 32 + mt * 16 + g;
#pragma unroll
            for (int nt = 0; nt < 8; nt++) {
                int c = col0 + warpN * 64 + nt * 8 + 2 * tg;
                C[(size_t)c * N + r]           = to_tf32(acc[mt][nt][0]);
                C[(size_t)(c + 1) * N + r]     = to_tf32(acc[mt][nt][1]);
                C[(size_t)c * N + r + 8]       = to_tf32(acc[mt][nt][2]);
                C[(size_t)(c + 1) * N + r + 8] = to_tf32(acc[mt][nt][3]);
            }
        }
    } else {
#pragma unroll
        for (int mt = 0; mt < 2; mt++) {
            int r = row0 + warpM * 32 + mt * 16 + g;
#pragma unroll
            for (int nt = 0; nt < 8; nt++) {
                int c = col0 + warpN * 64 + nt * 8 + 2 * tg;
                *(float2*)&C[(size_t)r * N + c]       = make_float2(acc[mt][nt][0], acc[mt][nt][1]);
                *(float2*)&C[(size_t)(r + 8) * N + c] = make_float2(acc[mt][nt][2], acc[mt][nt][3]);
            }
        }
    }
}

// ---------------- RoPE (in-place; K output tf32-rounded) ----------------
__global__ void rope_kernel(float* __restrict__ Q, float* __restrict__ K) {
    int idx = blockIdx.x * blockDim.x + threadIdx.x;
    int j = idx & 63;
    int h = (idx >> 6) & (NH - 1);
    int t = idx >> 10;

    float expo   = (float)(2 * j) * (1.0f / 128.0f);
    float invfrq = expf(-expo * 9.210340371976184f);
    float ang    = (float)t * invfrq;
    float sv, cv;
    sincosf(ang, &sv, &cv);

    int base = t * HID + h * HD + j;
    float q1 = Q[base], q2 = Q[base + 64];
    Q[base]      = q1 * cv - q2 * sv;
    Q[base + 64] = q2 * cv + q1 * sv;
    float k1 = K[base], k2 = K[base + 64];
    K[base]      = to_tf32(k1 * cv - k2 * sv);
    K[base + 64] = to_tf32(k2 * cv + k1 * sv);
}

// ---------------- Flash attention (R14 structure + exp-before-barrier softmax) ----------------
#define QKROWB 512
#define QK_TILE_FLOATS (64 * 128)    // 8192
#define VT_TILE_FLOATS (128 * 64)    // 8192
#define SLD 68

#define FM_SMEM_FLOATS (QK_TILE_FLOATS + 2*QK_TILE_FLOATS + 2*VT_TILE_FLOATS + 64*SLD + 256 + 128)
#define FM_SMEM_BYTES  (FM_SMEM_FLOATS * 4)

__global__ __launch_bounds__(256, 1) void flash_mma_kernel(const float* __restrict__ Q,
                                                           const float* __restrict__ K,
                                                           const float* __restrict__ Vt) {
    extern __shared__ float sm[];
    float* Qs   = sm;                          // 64 x 128 swizzled
    float* Ks   = Qs + QK_TILE_FLOATS;         // 2 stages
    float* Vts  = Ks + 2 * QK_TILE_FLOATS;     // 2 stages, 128 x 64 swizzled
    float* Ss   = Vts + 2 * VT_TILE_FLOATS;    // 64 x SLD (holds P)
    float* rmax = Ss + 64 * SLD;               // [2 bufs][2 halves][64]
    float* rsum = rmax + 256;                  // [2 halves][64] (epilogue only)

    const int qb = gridDim.x - 1 - blockIdx.x;
    const int h  = blockIdx.y;
    const int tid  = threadIdx.x;
    const int lane = tid & 31, warp = tid >> 5;
    const int g = lane >> 2, tg = lane & 3;
    const int wm = warp >> 1, wn = warp & 1;
    const int m0 = wm * 16;
    const int qrow0 = qb * 64;
    const float scale = 0.08838834764831845f * 1.4426950408889634f;
    const int barid = 1 + wm;
    const int r0 = m0 + g, r1 = m0 + g + 8;

    const int l8 = lane & 7;
    const int a_m  = m0 + l8 + (((lane >> 3) & 1) << 3);
    const int a_cs = (lane >> 4) & 1;
    const int b_n  = wn * 32 + l8 + (((lane >> 4) & 1) << 3);
    const int v_n  = wn * 64 + l8 + (((lane >> 4) & 1) << 3);
    const int b_cs = (lane >> 3) & 1;

    const u32 qsmB = (u32)__cvta_generic_to_shared(Qs);
    const u32 ksmB = (u32)__cvta_generic_to_shared(Ks);
    const u32 vsmB = (u32)__cvta_generic_to_shared(Vts);
    const u32 ssmB = (u32)__cvta_generic_to_shared(Ss);

    for (int i = tid; i < 64 * 32; i += 256) {
        int r = i >> 5, cc = i & 31;
        float4 v = *(const float4*)&Q[(size_t)(qrow0 + r) * HID + h * HD + cc * 4];
        v.x = to_tf32(v.x * scale); v.y = to_tf32(v.y * scale);
        v.z = to_tf32(v.z * scale); v.w = to_tf32(v.w * scale);
        *(float4*)((char*)Qs + r * QKROWB + ((cc ^ (r & 7)) << 4)) = v;
    }

#pragma unroll
    for (int t = 0; t < 8; t++) {
        int i = tid + t * 256;
        {
            int r = i >> 5, cc = i & 31;
            cp_async16(ksmB + (u32)(r * QKROWB + ((cc ^ (r & 7)) << 4)),
                       &K[(size_t)r * HID + h * HD + cc * 4]);
        }
        {
            int r = i >> 4, cc = i & 15;
            cp_async16(vsmB + (u32)(r * 256 + ((cc ^ (r & 7)) << 4)),
                       &Vt[(size_t)(h * HD + r) * S_LEN + cc * 4]);
        }
    }
    cp_commit();

    float oac[8][4];
#pragma unroll
    for (int nt = 0; nt < 8; nt++)
#pragma unroll
        for (int r = 0; r < 4; r++) oac[nt][r] = 0.f;
    float m_i0 = -1e30f, m_i1 = -1e30f, l_i0 = 0.f, l_i1 = 0.f;

    for (int kb = 0; kb <= qb; kb++) {
        int st = kb & 1;
        cp_wait0();
        __syncthreads();

        if (kb < qb) {
            int krow0 = (kb + 1) * 64;
            u32 ko = ksmB + (u32)((st ^ 1) * QK_TILE_FLOATS * 4);
            u32 vo = vsmB + (u32)((st ^ 1) * VT_TILE_FLOATS * 4);
#pragma unroll
            for (int t = 0; t < 8; t++) {
                int i = tid + t * 256;
                {
                    int r = i >> 5, cc = i & 31;
                    cp_async16(ko + (u32)(r * QKROWB + ((cc ^ (r & 7)) << 4)),
                               &K[(size_t)(krow0 + r) * HID + h * HD + cc * 4]);
                }
                {
                    int r = i >> 4, cc = i & 15;
                    cp_async16(vo + (u32)(r * 256 + ((cc ^ (r & 7)) << 4)),
                               &Vt[(size_t)(h * HD + r) * S_LEN + krow0 + cc * 4]);
                }
            }
            cp_commit();
        }

        const u32 kStage = ksmB + (u32)(st * QK_TILE_FLOATS * 4);
        const u32 vStage = vsmB + (u32)(st * VT_TILE_FLOATS * 4);

        // ---- S = Q @ K^T (regs) ----
        float sac[4][4];
#pragma unroll
        for (int nt = 0; nt < 4; nt++)
#pragma unroll
            for (int r = 0; r < 4; r++) sac[nt][r] = 0.f;

        {
            u32 qa[2][4], kf[2][4][2];
            ldsm4(qa[0][0], qa[0][1], qa[0][2], qa[0][3],
                  qsmB + (u32)(a_m * QKROWB + ((a_cs ^ l8) << 4)));
#pragma unroll
            for (int p = 0; p < 2; p++)
                ldsm4(kf[0][2 * p][0], kf[0][2 * p][1], kf[0][2 * p + 1][0], kf[0][2 * p + 1][1],
                      kStage + (u32)((b_n + p * 16) * QKROWB + ((b_cs ^ l8) << 4)));
#pragma unroll
            for (int kk = 0; kk < 16; kk++) {
                const int cur = kk & 1, nxt = cur ^ 1;
                if (kk < 15) {
                    const int c = 2 * (kk + 1);
                    ldsm4(qa[nxt][0], qa[nxt][1], qa[nxt][2], qa[nxt][3],
                          qsmB + (u32)(a_m * QKROWB + (((c + a_cs) ^ l8) << 4)));
#pragma unroll
                    for (int p = 0; p < 2; p++)
                        ldsm4(kf[nxt][2 * p][0], kf[nxt][2 * p][1], kf[nxt][2 * p + 1][0], kf[nxt][2 * p + 1][1],
                              kStage + (u32)((b_n + p * 16) * QKROWB + (((c + b_cs) ^ l8) << 4)));
                }
#pragma unroll
                for (int nt = 0; nt < 4; nt++)
                    mma_tf32(sac[nt], qa[cur], kf[cur][nt]);
            }
        }

        // ---- causal mask (regs) ----
        if (kb == qb) {
#pragma unroll
            for (int nt = 0; nt < 4; nt++) {
                int col = wn * 32 + nt * 8 + 2 * tg;
                if (col     > r0) sac[nt][0] = -1e30f;
                if (col + 1 > r0) sac[nt][1] = -1e30f;
                if (col     > r1) sac[nt][2] = -1e30f;
                if (col + 1 > r1) sac[nt][3] = -1e30f;
            }
        }

        // ---- softmax: local max + local exps BEFORE the barrier; correct after ----
        float mx0 = -1e30f, mx1 = -1e30f;
#pragma unroll
        for (int nt = 0; nt < 4; nt++) {
            mx0 = fmaxf(mx0, fmaxf(sac[nt][0], sac[nt][1]));
            mx1 = fmaxf(mx1, fmaxf(sac[nt][2], sac[nt][3]));
        }
        mx0 = fmaxf(mx0, __shfl_xor_sync(0xffffffffu, mx0, 1));
        mx0 = fmaxf(mx0, __shfl_xor_sync(0xffffffffu, mx0, 2));
        mx1 = fmaxf(mx1, __shfl_xor_sync(0xffffffffu, mx1, 1));
        mx1 = fmaxf(mx1, __shfl_xor_sync(0xffffffffu, mx1, 2));
        float* rb = rmax + (kb & 1) * 128;
        if (tg == 0) {
            rb[wn * 64 + r0] = mx0;
            rb[wn * 64 + r1] = mx1;
        }

        // exps relative to LOCAL half-row max (independent of barrier)
        float pp[4][4];
        float s0 = 0.f, s1 = 0.f;
#pragma unroll
        for (int nt = 0; nt < 4; nt++) {
            pp[nt][0] = fexp2(sac[nt][0] - mx0);
            pp[nt][1] = fexp2(sac[nt][1] - mx0);
            pp[nt][2] = fexp2(sac[nt][2] - mx1);
            pp[nt][3] = fexp2(sac[nt][3] - mx1);
            s0 += pp[nt][0] + pp[nt][1];
            s1 += pp[nt][2] + pp[nt][3];
        }
        s0 += __shfl_xor_sync(0xffffffffu, s0, 1);
        s0 += __shfl_xor_sync(0xffffffffu, s0, 2);
        s1 += __shfl_xor_sync(0xffffffffu, s1, 1);
        s1 += __shfl_xor_sync(0xffffffffu, s1, 2);

        bar_pair(barid);
        float mnew0 = fmaxf(m_i0, fmaxf(rb[r0], rb[64 + r0]));
        float mnew1 = fmaxf(m_i1, fmaxf(rb[r1], rb[64 + r1]));
        float alpha0 = fexp2(m_i0 - mnew0), alpha1 = fexp2(m_i1 - mnew1);
        float corr0 = fexp2(mx0 - mnew0), corr1 = fexp2(mx1 - mnew1);

        // correction multiply + tf32 round + store P
#pragma unroll
        for (int nt = 0; nt < 4; nt++) {
            int col = wn * 32 + nt * 8 + 2 * tg;
            Ss[r0 * SLD + col]     = to_tf32(pp[nt][0] * corr0);
            Ss[r0 * SLD + col + 1] = to_tf32(pp[nt][1] * corr0);
            Ss[r1 * SLD + col]     = to_tf32(pp[nt][2] * corr1);
            Ss[r1 * SLD + col + 1] = to_tf32(pp[nt][3] * corr1);
        }
        l_i0 = l_i0 * alpha0 + s0 * corr0;
        l_i1 = l_i1 * alpha1 + s1 * corr1;
        m_i0 = mnew0; m_i1 = mnew1;
        bar_pair(barid);   // P visible to pair before ldmatrix reads

        // ---- O = O*alpha + P @ Vt^T : all ldmatrix ----
#pragma unroll
        for (int nt = 0; nt < 8; nt++) {
            oac[nt][0] *= alpha0; oac[nt][1] *= alpha0;
            oac[nt][2] *= alpha1; oac[nt][3] *= alpha1;
        }
        {
            u32 pa[2][4], vf[2][8][2];
            ldsm4(pa[0][0], pa[0][1], pa[0][2], pa[0][3],
                  ssmB + (u32)((a_m * SLD + a_cs * 4) << 2));
#pragma unroll
            for (int p = 0; p < 4; p++)
                ldsm4(vf[0][2 * p][0], vf[0][2 * p][1], vf[0][2 * p + 1][0], vf[0][2 * p + 1][1],
                      vStage + (u32)((v_n + p * 16) * 256 + ((b_cs ^ l8) << 4)));
#pragma unroll
            for (int kk = 0; kk < 8; kk++) {
                const int cur = kk & 1, nxt = cur ^ 1;
                if (kk < 7) {
                    const int k0 = (kk + 1) * 8;
                    const int c = 2 * (kk + 1);
                    ldsm4(pa[nxt][0], pa[nxt][1], pa[nxt][2], pa[nxt][3],
                          ssmB + (u32)((a_m * SLD + k0 + a_cs * 4) << 2));
#pragma unroll
                    for (int p = 0; p < 4; p++)
                        ldsm4(vf[nxt][2 * p][0], vf[nxt][2 * p][1], vf[nxt][2 * p + 1][0], vf[nxt][2 * p + 1][1],
                              vStage + (u32)((v_n + p * 16) * 256 + (((c + b_cs) ^ l8) << 4)));
                }
#pragma unroll
                for (int nt = 0; nt < 8; nt++)
                    mma_tf32(oac[nt], pa[cur], vf[cur][nt]);
            }
        }
    }

    // combine l halves once
    if (tg == 0) {
        rsum[wn * 64 + r0] = l_i0;
        rsum[wn * 64 + r1] = l_i1;
    }
    bar_pair(barid);
    float inv0 = 1.0f / (rsum[r0] + rsum[64 + r0]);
    float inv1 = 1.0f / (rsum[r1] + rsum[64 + r1]);
#pragma unroll
    for (int nt = 0; nt < 8; nt++) {
        int col = wn * 64 + nt * 8 + 2 * tg;
        int gr0 = qrow0 + r0, gr1 = qrow0 + r1;
        float2 w0 = make_float2(to_tf32(oac[nt][0] * inv0), to_tf32(oac[nt][1] * inv0));
        float2 w1 = make_float2(to_tf32(oac[nt][2] * inv1), to_tf32(oac[nt][3] * inv1));
        *(float2*)&g_AO[(size_t)gr0 * HID + h * HD + col] = w0;
        *(float2*)&g_AO[(size_t)gr1 * HID + h * HD + col] = w1;
    }
}

// ---------------- launch ----------------
extern "C" void kernel_launch(void* const* d_in, const int* in_sizes, int n_in,
                              void* d_out, int out_size) {
    const float* X  = (const float*)d_in[0];
    const float* wq = (const float*)d_in[1];
    const float* wk = (const float*)d_in[2];
    const float* wv = (const float*)d_in[3];
    const float* wo = (const float*)d_in[4];
    float* out = (float*)d_out;

    float *Q, *K, *Vt, *AO, *Xt, *Wq, *Wk, *Wv, *Wo;
    cudaGetSymbolAddress((void**)&Q,  g_Q);
    cudaGetSymbolAddress((void**)&K,  g_K);
    cudaGetSymbolAddress((void**)&Vt, g_Vt);
    cudaGetSymbolAddress((void**)&AO, g_AO);
    cudaGetSymbolAddress((void**)&Xt, g_Xt);
    cudaGetSymbolAddress((void**)&Wq, g_Wq);
    cudaGetSymbolAddress((void**)&Wk, g_Wk);
    cudaGetSymbolAddress((void**)&Wv, g_Wv);
    cudaGetSymbolAddress((void**)&Wo, g_Wo);

    cudaFuncSetAttribute(tf32_gemm_ldsm<true>, cudaFuncAttributeMaxDynamicSharedMemorySize,
                         GEMM_SMEM_BYTES);
    cudaFuncSetAttribute(tf32_gemm_ldsm<false>, cudaFuncAttributeMaxDynamicSharedMemorySize,
                         GEMM_SMEM_BYTES);
    cudaFuncSetAttribute(flash_mma_kernel, cudaFuncAttributeMaxDynamicSharedMemorySize,
                         FM_SMEM_BYTES);

    prepass_kernel<<<dim3(64, 64, 5), dim3(32, 8)>>>(
        X, Xt, wq, Wq, wk, Wk, wv, Wv, wo, Wo);

    tf32_gemm_ldsm<true><<<dim3(16, 16, 3), 256, GEMM_SMEM_BYTES>>>(
        Xt, Wq, Wk, Wv, Q, K, Vt);

    rope_kernel<<<(S_LEN * NH * 64) / 256, 256>>>(Q, K);

    flash_mma_kernel<<<dim3(S_LEN / 64, NH), 256, FM_SMEM_BYTES>>>(Q, K, Vt);

    tf32_gemm_ldsm<false><<<dim3(16, 16, 1), 256, GEMM_SMEM_BYTES>>>(
        AO, Wo, Wo, Wo, out, out, out);

    (void)in_sizes; (void)n_in; (void)out_size;
}